// round 2
// baseline (speedup 1.0000x reference)
#include <cuda_runtime.h>
#include <cuda_bf16.h>
#include <math.h>

#define NMAX 50000
#define EMAX 1600000
#define FIN  128
#define FOUT 64
#define ALPHA 0.2f

// ---------------- scratch (device globals; no allocation) ----------------
__device__ float g_h[NMAX * FOUT];       // h = input @ W
__device__ float g_hprime[NMAX * FOUT];  // segment sum accumulator
__device__ float g_hcol[NMAX];           // h . a1l
__device__ float g_ha2r[NMAX];           // h . a2r
__device__ float g_pha1r[NMAX];          // p_h . (W a1r)
__device__ float g_nha2l[NMAX];          // new_h . (W a2l)
__device__ float g_ecsm[NMAX];           // col softmax workspace/result
__device__ float g_segmax[NMAX];
__device__ float g_segsum[NMAX];
__device__ float g_erowsum[NMAX];
__device__ float g_edge_e[EMAX];
__device__ float g_v2[FIN], g_v3[FIN];   // W@a1r, W@a2l

// ---------------- small vectors: v2 = W @ a1r, v3 = W @ a2l ----------------
__global__ void k_vec(const float* __restrict__ W,
                      const float* __restrict__ a1,
                      const float* __restrict__ a2) {
    int k = threadIdx.x;  // 128 threads
    float s2 = 0.f, s3 = 0.f;
#pragma unroll 8
    for (int j = 0; j < FOUT; j++) {
        float w = W[k * FOUT + j];
        s2 += w * a1[FOUT + j];
        s3 += w * a2[j];
    }
    g_v2[k] = s2; g_v3[k] = s3;
}

// ---------------- zeroing (graph-replay safe reset) ----------------
__global__ void k_zero(int n) {
    int i = blockIdx.x * blockDim.x + threadIdx.x;
    int n16 = n * (FOUT / 4);
    if (i < n16) ((float4*)g_hprime)[i] = make_float4(0.f, 0.f, 0.f, 0.f);
    if (i < n) {
        g_segmax[i] = 0.f;
        g_segsum[i] = 0.f;
        g_erowsum[i] = 0.f;
    }
}

// ---------------- GEMM: h = input @ W (N x 128 x 64) + hcol/ha2r epilogue ----
// Block: 256 threads, tile 64 rows x 64 cols, K chunked by 64.
// Thread (cg = t&15, rg = t>>4): 4 rows (4*rg..) x 4 cols (4*cg..), 16 acc.
#define XS_PITCH 65
__global__ void k_gemm(const float* __restrict__ X,
                       const float* __restrict__ W,
                       const float* __restrict__ a1,
                       const float* __restrict__ a2, int n) {
    __shared__ float Ws[64 * 64];            // 16 KB  (Ws[k][col])
    __shared__ float Xs[64 * XS_PITCH];      // 16.25 KB (Xs[row][k])
    int tid = threadIdx.x;
    int cg = tid & 15, rg = tid >> 4;
    long row0 = (long)blockIdx.x * 64;
    int rem = n - (int)row0; if (rem > 64) rem = 64;

    float acc[4][4] = {};
    for (int kb = 0; kb < FIN; kb += 64) {
        // stage W chunk: Ws[k][c] = W[(kb+k)*64 + c]; 64x64 floats = 1024 float4
        {
            int k = tid >> 2, c4 = tid & 3;            // 256 threads -> 64x4
            float4 wv0 = ((const float4*)(W + (kb + k) * FOUT))[c4];
            ((float4*)(Ws + k * 64))[c4] = wv0;
            float4 wv1 = ((const float4*)(W + (kb + k) * FOUT))[c4 + 4];
            ((float4*)(Ws + k * 64))[c4 + 4] = wv1;
            // covers 8 float4 per (k); need 16 per k. Do remaining 8:
            float4 wv2 = ((const float4*)(W + (kb + k) * FOUT))[c4 + 8];
            ((float4*)(Ws + k * 64))[c4 + 8] = wv2;
            float4 wv3 = ((const float4*)(W + (kb + k) * FOUT))[c4 + 12];
            ((float4*)(Ws + k * 64))[c4 + 12] = wv3;
        }
        // stage X chunk: Xs[row][k] = X[(row0+row)*128 + kb + k]
        {
            int row = tid >> 2, k16 = tid & 3;         // each thread: 4 float4 = 16 k
            if (row < rem) {
                const float4* src = (const float4*)(X + (row0 + row) * FIN + kb);
#pragma unroll
                for (int j = 0; j < 4; j++) {
                    float4 xv = src[k16 * 4 + j];
                    float* d = Xs + row * XS_PITCH + k16 * 16 + j * 4;
                    d[0] = xv.x; d[1] = xv.y; d[2] = xv.z; d[3] = xv.w;
                }
            }
        }
        __syncthreads();
#pragma unroll 8
        for (int k = 0; k < 64; k++) {
            float4 wv = ((const float4*)(Ws + k * 64))[cg];
            float x0 = Xs[(rg * 4 + 0) * XS_PITCH + k];
            float x1 = Xs[(rg * 4 + 1) * XS_PITCH + k];
            float x2 = Xs[(rg * 4 + 2) * XS_PITCH + k];
            float x3 = Xs[(rg * 4 + 3) * XS_PITCH + k];
            acc[0][0] += x0 * wv.x; acc[0][1] += x0 * wv.y; acc[0][2] += x0 * wv.z; acc[0][3] += x0 * wv.w;
            acc[1][0] += x1 * wv.x; acc[1][1] += x1 * wv.y; acc[1][2] += x1 * wv.z; acc[1][3] += x1 * wv.w;
            acc[2][0] += x2 * wv.x; acc[2][1] += x2 * wv.y; acc[2][2] += x2 * wv.z; acc[2][3] += x2 * wv.w;
            acc[3][0] += x3 * wv.x; acc[3][1] += x3 * wv.y; acc[3][2] += x3 * wv.z; acc[3][3] += x3 * wv.w;
        }
        __syncthreads();
    }
    // write h
#pragma unroll
    for (int r = 0; r < 4; r++) {
        int row = rg * 4 + r;
        if (row < rem) {
            float4 o; o.x = acc[r][0]; o.y = acc[r][1]; o.z = acc[r][2]; o.w = acc[r][3];
            ((float4*)(g_h + (row0 + row) * FOUT))[cg] = o;
        }
    }
    // epilogue: hcol[row] = h.a1l, ha2r[row] = h.a2r (reduce over 16 cg lanes)
    float a1l[4], a2r[4];
#pragma unroll
    for (int j = 0; j < 4; j++) {
        a1l[j] = a1[cg * 4 + j];
        a2r[j] = a2[FOUT + cg * 4 + j];
    }
    float s1[4], s4[4];
#pragma unroll
    for (int r = 0; r < 4; r++) {
        s1[r] = acc[r][0] * a1l[0] + acc[r][1] * a1l[1] + acc[r][2] * a1l[2] + acc[r][3] * a1l[3];
        s4[r] = acc[r][0] * a2r[0] + acc[r][1] * a2r[1] + acc[r][2] * a2r[2] + acc[r][3] * a2r[3];
    }
#pragma unroll
    for (int off = 8; off > 0; off >>= 1) {
#pragma unroll
        for (int r = 0; r < 4; r++) {
            s1[r] += __shfl_xor_sync(0xFFFFFFFFu, s1[r], off);
            s4[r] += __shfl_xor_sync(0xFFFFFFFFu, s4[r], off);
        }
    }
    if (cg == 0) {
#pragma unroll
        for (int r = 0; r < 4; r++) {
            int row = rg * 4 + r;
            if (row < rem) {
                g_hcol[row0 + row] = s1[r];
                g_ha2r[row0 + row] = s4[r];
            }
        }
    }
}

// ---------------- per-row dot products: pha1r, nha2l ----------------
__global__ void k_dots(const float* __restrict__ P,
                       const float* __restrict__ NH, int n) {
    int warp = (blockIdx.x * blockDim.x + threadIdx.x) >> 5;
    int lane = threadIdx.x & 31;
    if (warp >= n) return;
    float4 pv = ((const float4*)(P + (long)warp * FIN))[lane];
    float4 nv = ((const float4*)(NH + (long)warp * FIN))[lane];
    float4 v2 = ((const float4*)g_v2)[lane];
    float4 v3 = ((const float4*)g_v3)[lane];
    float s_pha1 = pv.x * v2.x + pv.y * v2.y + pv.z * v2.z + pv.w * v2.w;
    float s_nha2 = nv.x * v3.x + nv.y * v3.y + nv.z * v3.z + nv.w * v3.w;
#pragma unroll
    for (int o = 16; o > 0; o >>= 1) {
        s_pha1 += __shfl_down_sync(0xFFFFFFFFu, s_pha1, o);
        s_nha2 += __shfl_down_sync(0xFFFFFFFFu, s_nha2, o);
    }
    if (lane == 0) {
        g_pha1r[warp] = s_pha1;
        g_nha2l[warp] = s_nha2;
    }
}

// ---------------- column softmax passes ----------------
__global__ void k_col1(const int* __restrict__ edge_col0,
                       const int* __restrict__ row_i, int n) {
    int i = blockIdx.x * blockDim.x + threadIdx.x;
    if (i >= n) return;
    float cs = g_hcol[edge_col0[i]] + g_pha1r[i];
    float lr = cs > 0.f ? cs : ALPHA * cs;
    float e = expf(-lr);
    g_ecsm[i] = e;
    atomicMax((int*)&g_segmax[row_i[i]], __float_as_int(e));  // e > 0 always
}
__global__ void k_col2(const int* __restrict__ row_i, int n) {
    int i = blockIdx.x * blockDim.x + threadIdx.x;
    if (i >= n) return;
    float ex = expf(g_ecsm[i] - g_segmax[row_i[i]]);
    g_ecsm[i] = ex;
    atomicAdd(&g_segsum[row_i[i]], ex);
}
__global__ void k_col3(const int* __restrict__ row_i, int n) {
    int i = blockIdx.x * blockDim.x + threadIdx.x;
    if (i >= n) return;
    g_ecsm[i] = g_ecsm[i] / (g_segsum[row_i[i]] + 1e-16f);
}

// ---------------- fused edge kernel: scores + rowsum + v4 red scatter -------
// 16 threads per edge; sub-leader (t==0) computes ee, broadcasts via shfl.
__global__ void k_edge(const int* __restrict__ edge0,
                       const int* __restrict__ edge1,
                       const int* __restrict__ row_resort, int E) {
    int e = (blockIdx.x * blockDim.x + threadIdx.x) >> 4;
    int t = threadIdx.x & 15;
    if (e >= E) return;
    int dst = edge0[e];
    int src = edge1[e];
    float ee = 0.f;
    if (t == 0) {
        int rr = row_resort[e];
        float rs = g_nha2l[rr] + g_ha2r[src];
        float lr = rs > 0.f ? rs : ALPHA * rs;
        ee = expf(-lr) * g_ecsm[rr];
        g_edge_e[e] = ee;
        atomicAdd(&g_erowsum[dst], ee);
    }
    int lane = threadIdx.x & 31;
    ee = __shfl_sync(0xFFFFFFFFu, ee, lane & 16);  // broadcast from t==0 of half
    float4 hv = *(const float4*)(g_h + (long)src * FOUT + t * 4);
    float4 r;
    r.x = ee * hv.x; r.y = ee * hv.y; r.z = ee * hv.z; r.w = ee * hv.w;
    float* dp = g_hprime + (long)dst * FOUT + t * 4;
    asm volatile("red.global.add.v4.f32 [%0], {%1, %2, %3, %4};"
                 :: "l"(__cvta_generic_to_global(dp)),
                    "f"(r.x), "f"(r.y), "f"(r.z), "f"(r.w)
                 : "memory");
}

// ---------------- attention output ----------------
__global__ void k_att(const int* __restrict__ edge0,
                      float* __restrict__ att_out, int E) {
    int e = blockIdx.x * blockDim.x + threadIdx.x;
    if (e >= E) return;
    float s = g_erowsum[edge0[e]];
    if (s == 0.f) s = 1.f;
    att_out[e] = g_edge_e[e] / s;
}

// ---------------- finalize: out = elu(h_prime / e_rowsum) ----------------
__global__ void k_final(float* __restrict__ out, int n) {
    int i4 = blockIdx.x * blockDim.x + threadIdx.x;  // one float4 each
    if (i4 >= n * (FOUT / 4)) return;
    int row = i4 >> 4;
    float s = g_erowsum[row];
    if (s == 0.f) s = 1.f;
    float inv = 1.f / s;
    float4 v = ((const float4*)g_hprime)[i4];
    v.x *= inv; v.y *= inv; v.z *= inv; v.w *= inv;
    v.x = v.x > 0.f ? v.x : expm1f(v.x);
    v.y = v.y > 0.f ? v.y : expm1f(v.y);
    v.z = v.z > 0.f ? v.z : expm1f(v.z);
    v.w = v.w > 0.f ? v.w : expm1f(v.w);
    ((float4*)out)[i4] = v;
}

// ---------------- copy edge indices to output as float ----------------
__global__ void k_edgecopy(const int* __restrict__ edge, float* __restrict__ out,
                           int n2e) {
    int i = blockIdx.x * blockDim.x + threadIdx.x;
    if (i < n2e) out[i] = (float)edge[i];
}

extern "C" void kernel_launch(void* const* d_in, const int* in_sizes, int n_in,
                              void* d_out, int out_size) {
    const float* input      = (const float*)d_in[0];
    const float* p_h        = (const float*)d_in[1];
    const float* new_h      = (const float*)d_in[2];
    const int*   edge       = (const int*)d_in[3];
    const int*   edge_col   = (const int*)d_in[4];
    const int*   row_i      = (const int*)d_in[5];
    const int*   row_resort = (const int*)d_in[6];
    const float* W          = (const float*)d_in[8];
    const float* a1         = (const float*)d_in[9];
    const float* a2         = (const float*)d_in[10];

    int N = in_sizes[0] / FIN;
    int E = in_sizes[3] / 2;
    const int* edge0 = edge;
    const int* edge1 = edge + E;
    float* out = (float*)d_out;

    long n64 = (long)N * FOUT;
    int full = (out_size >= (int)(n64 + 2L * E + E)) ? 1 : 0;
    float* out_edges = full ? out + n64 : nullptr;
    float* out_att   = full ? out + n64 + 2L * E : out;

    const int T = 256;
    k_zero<<<(N * 16 + T - 1) / T, T>>>(N);
    k_vec<<<1, 128>>>(W, a1, a2);
    k_gemm<<<(N + 63) / 64, 256>>>(input, W, a1, a2, N);
    k_dots<<<(N * 32 + T - 1) / T, T>>>(p_h, new_h, N);

    k_col1<<<(N + T - 1) / T, T>>>(edge_col, row_i, N);
    k_col2<<<(N + T - 1) / T, T>>>(row_i, N);
    k_col3<<<(N + T - 1) / T, T>>>(row_i, N);

    k_edge<<<(E * 16 + T - 1) / T, T>>>(edge0, edge1, row_resort, E);

    if (full) {
        k_att<<<(E + T - 1) / T, T>>>(edge0, out_att, E);
        k_edgecopy<<<(2 * E + T - 1) / T, T>>>(edge, out_edges, 2 * E);
    }
    k_final<<<((N * FOUT / 4) + T - 1) / T, T>>>(out, N);
}